// round 17
// baseline (speedup 1.0000x reference)
#include <cuda_runtime.h>
#include <cstddef>
#include <cstdint>
#include <math.h>

#define BB   256
#define VV   50
#define CC   40
#define DD   256
#define HH   256
#define TT   1000

// ---------------- scratch buffer (float offsets) ----------------
constexpr size_t OFF_AB   = 0;            // 1000
constexpr size_t OFF_SA   = 1024;         // 256
constexpr size_t OFF_SB   = 1280;         // 256
constexpr size_t OFF_QP0  = 1536;         // 256
constexpr size_t OFF_CF   = 1792;         // 256
constexpr size_t OFF_BSUM = 2048;         // 1024
constexpr size_t OFF_B2   = 3072;         // 1024
constexpr size_t OFF_MF   = 4096;         // 256*256
constexpr size_t OFF_WOT  = 69632;        // 256*256
constexpr size_t OFF_W2   = 135168;       // 1024*256
constexpr size_t OFF_PK   = 397312;       // 256*256*4 floats (float4-packed w_hh)
constexpr size_t OFF_HID  = 659456;       // 12800*64
constexpr size_t OFF_VE   = 1478656;      // 12800*256
constexpr size_t OFF_G1   = 4755456;      // 12800*256
constexpr size_t OFF_KP   = 8032256;      // 12800*256
constexpr size_t OFF_VP   = 11309056;     // 12800*256
constexpr size_t OFF_O    = 14585856;     // 12800*256 (pre-out-proj attn outputs)
constexpr size_t OFF_XGV  = 17862656;     // 12800*1024
constexpr size_t OFF_XGG  = 30969856;     // 12800*1024
constexpr size_t OFF_H    = 44077056;     // 100*256 (rows 0..49 hv, 50..99 hg)
constexpr size_t OFF_H1   = 44102656;     // 100*1024
constexpr size_t OFF_H2   = 44205056;     // 100*1024
constexpr size_t OFF_PROB = 44307456;     // 100*2
constexpr size_t BUF_SIZE = 44307656;

__device__ float g_buf[BUF_SIZE];

__device__ __forceinline__ float sigf(float x) { return 1.0f / (1.0f + expf(-x)); }

#define FMA2(acc, a, b) \
    asm("fma.rn.f32x2 %0, %1, %2, %0;" : "+l"(acc) : "l"(a), "l"(b))

// ---------------- tiny prep kernels ----------------
__global__ void k_ab(const float* __restrict__ betas, float* __restrict__ ab) {
    if (threadIdx.x == 0) {
        float p = 1.0f;
        for (int i = 0; i < TT; i++) { p *= (1.0f - betas[i]); ab[i] = p; }
    }
}

__global__ void k_sab(const int* __restrict__ dt, const float* __restrict__ ab,
                      float* __restrict__ sa, float* __restrict__ sb) {
    int b = threadIdx.x;
    float a = ab[dt[b]];
    sa[b] = sqrtf(a);
    sb[b] = sqrtf(fmaxf(1.0f - a, 0.0f));
}

__global__ void k_prep(const float* __restrict__ wih, const float* __restrict__ bih,
                       const float* __restrict__ bhh, const float* __restrict__ ipw,
                       const float* __restrict__ ipb, const float* __restrict__ opb,
                       float* __restrict__ bsum, float* __restrict__ b2,
                       float* __restrict__ cf, float* __restrict__ qp0) {
    int j = blockIdx.x * 256 + threadIdx.x;
    if (j < 1024) {
        float acc = 0.0f;
        const float* wr = wih + (size_t)j * 256;
        for (int d = 0; d < 256; d++) acc += wr[d] * opb[d];
        bsum[j] = bih[j] + bhh[j];
        b2[j]   = acc + bih[j] + bhh[j];
    } else if (j < 1280) {
        int jj = j - 1024;
        float acc = 0.0f;
        const float* wr = ipw + (size_t)jj * 256;   // Wq row
        for (int d = 0; d < 256; d++) acc += wr[d] * opb[d];
        cf[jj] = acc + ipb[jj];
    } else if (j < 1536) {
        int jj = j - 1280;
        float acc = 0.0f;
        const float* wr = ipw + (size_t)jj * 256;
        for (int d = 0; d < 256; d++) acc += wr[d];
        qp0[jj] = 10000.0f * acc + ipb[jj];
    }
}

__global__ void k_two(const float* __restrict__ wo, float* __restrict__ wot) {
    int e = blockIdx.x, d = threadIdx.x;
    wot[e * 256 + d] = wo[d * 256 + e];     // wot[e,d] = Wo[d,e]
}

__global__ void k_pack(const float* __restrict__ whh, float4* __restrict__ pk) {
    int d = blockIdx.x, j = threadIdx.x;
    pk[d * 256 + j] = make_float4(whh[(0   + j) * 256 + d],
                                  whh[(256 + j) * 256 + d],
                                  whh[(512 + j) * 256 + d],
                                  whh[(768 + j) * 256 + d]);
}

// hid[r*64+k], r = v*256+b
__global__ void k_hid(const float* __restrict__ st, const float* __restrict__ tlw,
                      const float* __restrict__ tlb, float* __restrict__ hid) {
    int gid = blockIdx.x * 256 + threadIdx.x;
    int k = gid & 63;
    int r = gid >> 6;
    int v = r >> 8, b = r & 255;
    float tt = st[b * VV + v] * (1.0f / 180.0f);
    float x = tt * tlw[k] + tlb[k];
    hid[gid] = 1.0f - tanhf(x * x);
}

// ve (tenc already in place) += embedding gather; then gen1
__global__ void k_ve(const int* __restrict__ seqs, const float* __restrict__ emb,
                     const float* __restrict__ nn, const float* __restrict__ pn,
                     const float* __restrict__ sa, const float* __restrict__ sb,
                     float* __restrict__ ve, float* __restrict__ g1) {
    __shared__ int sidx[CC];
    int r = blockIdx.x;
    int d = threadIdx.x;
    int v = r >> 8, b = r & 255;
    if (d < CC) sidx[d] = seqs[(b * VV + v) * CC + d];
    __syncthreads();
    float acc = ve[(size_t)r * 256 + d];   // tenc
#pragma unroll 8
    for (int c = 0; c < CC; c++)
        acc += fmaxf(emb[(size_t)sidx[c] * 256 + d], 0.0f);
    ve[(size_t)r * 256 + d] = acc;
    size_t ni = ((size_t)b * VV + v) * 256 + d;
    g1[(size_t)r * 256 + d] = acc * (1.0f + sa[b]) + nn[ni] * sb[b] - pn[ni];
}

// ---------------- generic tiled SGEMM: C[M,N] = A[M,K] @ B[N,K]^T (+bias)(+relu) --------
__global__ void gemm_nt(const float* __restrict__ A, const float* __restrict__ B,
                        const float* __restrict__ bias, float* __restrict__ C,
                        int M, int N, int K, int relu) {
    __shared__ float As[16 * 68];
    __shared__ float Bs[16 * 68];
    int tid = threadIdx.x;
    int tx = tid & 15, ty = tid >> 4;
    int n0 = blockIdx.x * 64, m0 = blockIdx.y * 64;
    int lr = tid >> 2;            // 0..63
    int lk = (tid & 3) * 4;       // 0,4,8,12
    float acc[4][4] = {};
    for (int k0 = 0; k0 < K; k0 += 16) {
        __syncthreads();
        int ar = m0 + lr;
        float4 av = (ar < M) ? *reinterpret_cast<const float4*>(A + (size_t)ar * K + k0 + lk)
                             : make_float4(0.f, 0.f, 0.f, 0.f);
        float4 bv = *reinterpret_cast<const float4*>(B + (size_t)(n0 + lr) * K + k0 + lk);
        As[(lk + 0) * 68 + lr] = av.x;
        As[(lk + 1) * 68 + lr] = av.y;
        As[(lk + 2) * 68 + lr] = av.z;
        As[(lk + 3) * 68 + lr] = av.w;
        Bs[(lk + 0) * 68 + lr] = bv.x;
        Bs[(lk + 1) * 68 + lr] = bv.y;
        Bs[(lk + 2) * 68 + lr] = bv.z;
        Bs[(lk + 3) * 68 + lr] = bv.w;
        __syncthreads();
#pragma unroll
        for (int kk = 0; kk < 16; kk++) {
            float4 a = *reinterpret_cast<const float4*>(As + kk * 68 + ty * 4);
            float4 b = *reinterpret_cast<const float4*>(Bs + kk * 68 + tx * 4);
            acc[0][0] += a.x * b.x; acc[0][1] += a.x * b.y; acc[0][2] += a.x * b.z; acc[0][3] += a.x * b.w;
            acc[1][0] += a.y * b.x; acc[1][1] += a.y * b.y; acc[1][2] += a.y * b.z; acc[1][3] += a.y * b.w;
            acc[2][0] += a.z * b.x; acc[2][1] += a.z * b.y; acc[2][2] += a.z * b.z; acc[2][3] += a.z * b.w;
            acc[3][0] += a.w * b.x; acc[3][1] += a.w * b.y; acc[3][2] += a.w * b.z; acc[3][3] += a.w * b.w;
        }
    }
#pragma unroll
    for (int i = 0; i < 4; i++) {
        int row = m0 + ty * 4 + i;
        if (row < M) {
#pragma unroll
            for (int j = 0; j < 4; j++) {
                int col = n0 + tx * 4 + j;
                float vout = acc[i][j] + (bias ? bias[col] : 0.0f);
                if (relu) vout = fmaxf(vout, 0.0f);
                C[(size_t)row * N + col] = vout;
            }
        }
    }
}

// ---------------- fused attention step ----------------
#define ATTN_SHM_FLOATS (256*33*2 + 16*256 + 32*257 + 16*32 + 16*256)
#define ATTN_SHM_BYTES  (ATTN_SHM_FLOATS * 4)

__global__ void k_attn(int step, const float* __restrict__ kp, const float* __restrict__ vp,
                       float* __restrict__ O, const float* __restrict__ Mf,
                       const float* __restrict__ cf, const float* __restrict__ qp0) {
    extern __shared__ float sm[];
    float* kps = sm;                    // 256 keys x 32 hd, stride 33
    float* vps = kps + 256 * 33;
    float* oq  = vps + 256 * 33;        // 16 x 256 prev-O rows
    float* Ms  = oq + 16 * 256;         // 32 x 257 M rows for this head
    float* qps = Ms + 32 * 257;         // 16 x 32
    float* ss  = qps + 16 * 32;         // 16 x 256 scores

    int tid = threadIdx.x;
    int head = blockIdx.x, qt = blockIdx.y;
    int q0 = qt * 16;
    const float* kpv = kp + (size_t)step * (BB * DD);
    const float* vpv = vp + (size_t)step * (BB * DD);

    for (int idx = tid; idx < 256 * 32; idx += 256) {
        int k = idx >> 5, hd = idx & 31;
        kps[k * 33 + hd] = kpv[k * 256 + head * 32 + hd];
        vps[k * 33 + hd] = vpv[k * 256 + head * 32 + hd];
    }
    if (step > 0) {
        const float* Op = O + (size_t)(step - 1) * (BB * DD);
        for (int idx = tid; idx < 16 * 256; idx += 256)
            oq[idx] = Op[(q0 + (idx >> 8)) * 256 + (idx & 255)];
        for (int idx = tid; idx < 32 * 256; idx += 256) {
            int j = idx >> 8, e = idx & 255;
            Ms[j * 257 + e] = Mf[(head * 32 + j) * 256 + e];
        }
    }
    __syncthreads();

    int jl = tid & 31, qi = tid >> 5;
    if (step == 0) {
        float vq = qp0[head * 32 + jl];
        qps[qi * 32 + jl] = vq;
        qps[(qi + 8) * 32 + jl] = vq;
    } else {
        for (int qq = qi; qq < 16; qq += 8) {
            float acc = cf[head * 32 + jl];
            const float* orow = oq + qq * 256;
            const float* mrow = Ms + jl * 257;
#pragma unroll 8
            for (int e = 0; e < 256; e++) acc += orow[e] * mrow[e];
            qps[qq * 32 + jl] = acc;
        }
    }
    __syncthreads();

    {   // scores: one key per thread
        int k = tid;
        const float* krow = kps + k * 33;
#pragma unroll
        for (int q = 0; q < 16; q++) {
            const float* qrow = qps + q * 32;
            float acc = 0.0f;
#pragma unroll
            for (int hd = 0; hd < 32; hd++) acc += qrow[hd] * krow[hd];
            ss[q * 256 + k] = acc * 0.17677669529663687f;  // 1/sqrt(32)
        }
    }
    __syncthreads();

    {   // softmax over k; warp w handles q rows w and w+8
        int lane = tid & 31, w = tid >> 5;
        for (int q = w; q < 16; q += 8) {
            float* row = ss + q * 256;
            float vv[8];
            float mx = -1e30f;
#pragma unroll
            for (int m = 0; m < 8; m++) { vv[m] = row[lane + 32 * m]; mx = fmaxf(mx, vv[m]); }
#pragma unroll
            for (int o = 16; o; o >>= 1) mx = fmaxf(mx, __shfl_xor_sync(0xFFFFFFFFu, mx, o));
            float sum = 0.0f;
#pragma unroll
            for (int m = 0; m < 8; m++) { vv[m] = expf(vv[m] - mx); sum += vv[m]; }
#pragma unroll
            for (int o = 16; o; o >>= 1) sum += __shfl_xor_sync(0xFFFFFFFFu, sum, o);
            float inv = 1.0f / sum;
#pragma unroll
            for (int m = 0; m < 8; m++) row[lane + 32 * m] = vv[m] * inv;
        }
    }
    __syncthreads();

    {   // O = P @ Vp
        int hd = tid & 31, qi2 = tid >> 5;
        float* Oo = O + (size_t)step * (BB * DD);
        for (int qq = qi2; qq < 16; qq += 8) {
            const float* prow = ss + qq * 256;
            float acc = 0.0f;
#pragma unroll 8
            for (int k = 0; k < 256; k++) acc += prow[k] * vps[k * 33 + hd];
            Oo[(q0 + qq) * 256 + head * 32 + hd] = acc;
        }
    }
}

// ---------------- LSTM v4: 25 clusters x 2 CTAs, 4 chains per CTA, f32x2 FMA --------
// Cluster cid handles v0 = 2*cid, v1 = 2*cid+1; chains: {ve(v0), gen(v0), ve(v1), gen(v1)}.
// CTA rank r owns gate columns jglob = r*128 + j for ALL 4 chains.
// Thread (j, s): partial gate sums over d in [s*64, (s+1)*64).
// h stored duplicated (h,h) as f32x2 pairs -> weight float4 (i,f,g,o) natively provides
// the two f32x2 multiplicands; 8 fma.rn.f32x2 per d = 16 MACs, zero packing movs.
// s==0's weight slice (d 0..63, 128 KB) is smem-resident; s=1..3 stream from L2.
// DSMEM: each finisher broadcasts its (h,h) to the peer CTA; one cluster barrier/step.
#define LSTM_W_BYTES   (64 * 128 * 16)                 // 131072
#define LSTM_H_BYTES   (2 * 2 * 256 * 16)              // 16384
#define LSTM_P_BYTES   (512 * 18 * 4)                  // 36864
#define LSTM_SHM_BYTES (LSTM_W_BYTES + LSTM_H_BYTES + LSTM_P_BYTES)

__global__ void __launch_bounds__(512, 1) __cluster_dims__(2, 1, 1)
k_lstm(const float* __restrict__ xgv, const float* __restrict__ xgg,
       const float4* __restrict__ pk, float* __restrict__ hout) {
    extern __shared__ char smraw[];
    ulonglong2* wsm  = (ulonglong2*)smraw;                       // [64][128]
    ulonglong2* hdup = (ulonglong2*)(smraw + LSTM_W_BYTES);      // [buf][pair][256]
    float*      part = (float*)(smraw + LSTM_W_BYTES + LSTM_H_BYTES); // [512][18]

    int tid = threadIdx.x;
    int cid = blockIdx.x >> 1, r = blockIdx.x & 1;
    int v0 = cid * 2, v1 = v0 + 1;
    int j = tid & 127, s = tid >> 7;
    int jglob = r * 128 + j;

    // preload s=0 weight slice: pk[d][jglob] for d in [0,64)
    for (int idx = tid; idx < 64 * 128; idx += 512) {
        int d = idx >> 7, jj = idx & 127;
        wsm[idx] = ((const ulonglong2*)pk)[d * 256 + r * 128 + jj];
    }
    // zero h buffers
    {
        ulonglong2 z; z.x = 0; z.y = 0;
        for (int i = tid; i < 2 * 2 * 256; i += 512) hdup[i] = z;
    }
    __syncthreads();
    asm volatile("barrier.cluster.arrive.aligned;" ::: "memory");
    asm volatile("barrier.cluster.wait.aligned;"   ::: "memory");

    // finisher mapping: chain fch = s, gate col fj = j
    int fch = s, fj = j;
    const float* xp = ((fch & 1) ? xgg : xgg == xgv ? xgv : xgv) /*placeholder*/;
    xp = ((fch & 1) ? xgg : xgv) + (size_t)((fch >> 1) ? v1 : v0) * 256 * 1024 + r * 128 + fj;
    float cst = 0.0f;

    // weight stream pointer for s>0 (ulonglong2 view of float4)
    const ulonglong2* gw = (const ulonglong2*)pk + (size_t)(s * 64) * 256 + jglob;

    for (int t = 0; t < 256; t++) {
        int cur = t & 1, nxt = cur ^ 1;

        // prefetch x-gates (finisher)
        const float* xr = xp + (size_t)t * 1024;
        float xi = xr[0], xf = xr[256], xg_ = xr[512], xo = xr[768];

        // partial gate sums over this thread's 64-d slice, 4 chains via f32x2
        unsigned long long aIF0 = 0, aGO0 = 0, aIF1 = 0, aGO1 = 0;
        unsigned long long aIF2 = 0, aGO2 = 0, aIF3 = 0, aGO3 = 0;
        const ulonglong2* hA = hdup + (cur * 2 + 0) * 256 + s * 64;  // pair (c0,c1)
        const ulonglong2* hB = hdup + (cur * 2 + 1) * 256 + s * 64;  // pair (c2,c3)
        if (s == 0) {
            const ulonglong2* wp = wsm + j;
            for (int dd = 0; dd < 64; dd += 8) {
                ulonglong2 w[8];
#pragma unroll
                for (int k = 0; k < 8; k++) w[k] = wp[(dd + k) * 128];
#pragma unroll
                for (int k = 0; k < 8; k++) {
                    ulonglong2 ha = hA[dd + k], hb = hB[dd + k];
                    FMA2(aIF0, w[k].x, ha.x); FMA2(aGO0, w[k].y, ha.x);
                    FMA2(aIF1, w[k].x, ha.y); FMA2(aGO1, w[k].y, ha.y);
                    FMA2(aIF2, w[k].x, hb.x); FMA2(aGO2, w[k].y, hb.x);
                    FMA2(aIF3, w[k].x, hb.y); FMA2(aGO3, w[k].y, hb.y);
                }
            }
        } else {
            for (int dd = 0; dd < 64; dd += 8) {
                ulonglong2 w[8];
#pragma unroll
                for (int k = 0; k < 8; k++) w[k] = gw[(size_t)(dd + k) * 256];
#pragma unroll
                for (int k = 0; k < 8; k++) {
                    ulonglong2 ha = hA[dd + k], hb = hB[dd + k];
                    FMA2(aIF0, w[k].x, ha.x); FMA2(aGO0, w[k].y, ha.x);
                    FMA2(aIF1, w[k].x, ha.y); FMA2(aGO1, w[k].y, ha.y);
                    FMA2(aIF2, w[k].x, hb.x); FMA2(aGO2, w[k].y, hb.x);
                    FMA2(aIF3, w[k].x, hb.y); FMA2(aGO3, w[k].y, hb.y);
                }
            }
        }
        // store partials: row (j + c*128), offsets s*4 + {0,1}=IF, {2,3}=GO
        {
            float* p0 = part + (size_t)(j + 0 * 128) * 18 + s * 4;
            float* p1 = part + (size_t)(j + 1 * 128) * 18 + s * 4;
            float* p2 = part + (size_t)(j + 2 * 128) * 18 + s * 4;
            float* p3 = part + (size_t)(j + 3 * 128) * 18 + s * 4;
            *(unsigned long long*)(p0)     = aIF0;
            *(unsigned long long*)(p0 + 2) = aGO0;
            *(unsigned long long*)(p1)     = aIF1;
            *(unsigned long long*)(p1 + 2) = aGO1;
            *(unsigned long long*)(p2)     = aIF2;
            *(unsigned long long*)(p2 + 2) = aGO2;
            *(unsigned long long*)(p3)     = aIF3;
            *(unsigned long long*)(p3 + 2) = aGO3;
        }
        __syncthreads();

        // finish: every thread finalizes one (chain fch, col fj)
        {
            const float* q = part + (size_t)(fj + fch * 128) * 18;
            float gi = xi  + q[0] + q[4] + q[8]  + q[12];
            float gf = xf  + q[1] + q[5] + q[9]  + q[13];
            float gg = xg_ + q[2] + q[6] + q[10] + q[14];
            float go = xo  + q[3] + q[7] + q[11] + q[15];
            cst = sigf(gf) * cst + sigf(gi) * tanhf(gg);
            float h = sigf(go) * tanhf(cst);
            unsigned long long hd;
            asm("mov.b64 %0, {%1, %1};" : "=l"(hd) : "f"(h));
            int pair = fch >> 1, cip = fch & 1;
            unsigned long long* dst =
                (unsigned long long*)(hdup + (nxt * 2 + pair) * 256 + jglob) + cip;
            *dst = hd;  // local
            uint32_t la = (uint32_t)__cvta_generic_to_shared(dst);
            uint32_t ra;
            asm("mapa.shared::cluster.u32 %0, %1, %2;" : "=r"(ra) : "r"(la), "r"(r ^ 1));
            asm volatile("st.shared::cluster.b64 [%0], %1;" :: "r"(ra), "l"(hd) : "memory");
            if (t == 255) {
                int branch = fch & 1;
                int vv = (fch >> 1) ? v1 : v0;
                hout[(branch * VV + vv) * 256 + jglob] = h;
            }
        }
        asm volatile("barrier.cluster.arrive.aligned;" ::: "memory");
        asm volatile("barrier.cluster.wait.aligned;"   ::: "memory");
    }
}

// ---------------- logits + softmax over 2 classes ----------------
__global__ void k_logits(const float* __restrict__ h2, const float* __restrict__ cow,
                         const float* __restrict__ cob, float* __restrict__ probs) {
    int t = blockIdx.x * blockDim.x + threadIdx.x;
    if (t >= 100) return;
    const float* hr = h2 + (size_t)t * 1024;
    float l0 = cob[0], l1 = cob[1];
    for (int d = 0; d < 1024; d++) { l0 += hr[d] * cow[d]; l1 += hr[d] * cow[1024 + d]; }
    float m = fmaxf(l0, l1);
    float e0 = expf(l0 - m), e1 = expf(l1 - m);
    float s = e0 + e1;
    probs[t * 2 + 0] = e0 / s;
    probs[t * 2 + 1] = e1 / s;
}

// ---------------- output assembly: first 52224 floats ----------------
__global__ void k_out(const float* __restrict__ probs, float* __restrict__ out) {
    int i = blockIdx.x * 256 + threadIdx.x;
    if (i >= 52224) return;
    float val;
    if (i < 25600) {                       // res [B,V,2]
        int v = (i >> 1) % 50;
        val = probs[v * 2 + (i & 1)];
    } else if (i < 51200) {                // resg [B,V,2]
        int j = i - 25600;
        int v = (j >> 1) % 50;
        val = probs[(50 + v) * 2 + (j & 1)];
    } else if (i < 51712) {                // res[:, -1]
        val = probs[98 + (i & 1)];
    } else {                               // resg[:, -1]
        val = probs[198 + (i & 1)];
    }
    out[i] = val;
}

// ---------------- host launcher ----------------
extern "C" void kernel_launch(void* const* d_in, const int* in_sizes, int n_in,
                              void* d_out, int out_size) {
    (void)in_sizes; (void)n_in; (void)out_size;
    const int*   seqs = (const int*)  d_in[0];
    const float* st   = (const float*)d_in[1];
    const int*   dt   = (const int*)  d_in[2];
    const float* nn   = (const float*)d_in[3];
    const float* pn   = (const float*)d_in[4];
    const float* emb  = (const float*)d_in[5];
    const float* betas= (const float*)d_in[6];
    const float* tlw  = (const float*)d_in[7];
    const float* tlb  = (const float*)d_in[8];
    const float* tuw  = (const float*)d_in[9];
    const float* tub  = (const float*)d_in[10];
    const float* ipw  = (const float*)d_in[11];
    const float* ipb  = (const float*)d_in[12];
    const float* opw  = (const float*)d_in[13];
    const float* opb  = (const float*)d_in[14];
    const float* wih  = (const float*)d_in[15];
    const float* whh  = (const float*)d_in[16];
    const float* bih  = (const float*)d_in[17];
    const float* bhh  = (const float*)d_in[18];
    const float* c1w  = (const float*)d_in[19];
    const float* c1b  = (const float*)d_in[20];
    const float* c2w  = (const float*)d_in[21];
    const float* c2b  = (const float*)d_in[22];
    const float* cow  = (const float*)d_in[23];
    const float* cob  = (const float*)d_in[24];
    float* out = (float*)d_out;

    float* buf = nullptr;
    cudaGetSymbolAddress((void**)&buf, g_buf);
    float* ab   = buf + OFF_AB;
    float* sa   = buf + OFF_SA;
    float* sb   = buf + OFF_SB;
    float* qp0  = buf + OFF_QP0;
    float* cf   = buf + OFF_CF;
    float* bsum = buf + OFF_BSUM;
    float* b2   = buf + OFF_B2;
    float* Mf   = buf + OFF_MF;
    float* wot  = buf + OFF_WOT;
    float* W2   = buf + OFF_W2;
    float4* pk  = (float4*)(buf + OFF_PK);
    float* hid  = buf + OFF_HID;
    float* ve   = buf + OFF_VE;
    float* g1   = buf + OFF_G1;
    float* kp   = buf + OFF_KP;
    float* vp   = buf + OFF_VP;
    float* O    = buf + OFF_O;
    float* xgv  = buf + OFF_XGV;
    float* xgg  = buf + OFF_XGG;
    float* H    = buf + OFF_H;
    float* H1   = buf + OFF_H1;
    float* H2   = buf + OFF_H2;
    float* prob = buf + OFF_PROB;

    cudaFuncSetAttribute(k_attn, cudaFuncAttributeMaxDynamicSharedMemorySize, ATTN_SHM_BYTES);
    cudaFuncSetAttribute(k_lstm, cudaFuncAttributeMaxDynamicSharedMemorySize, LSTM_SHM_BYTES);

    // --- prep ---
    k_ab<<<1, 32>>>(betas, ab);
    k_sab<<<1, 256>>>(dt, ab, sa, sb);
    k_prep<<<6, 256>>>(wih, bih, bhh, ipw, ipb, opb, bsum, b2, cf, qp0);
    k_two<<<256, 256>>>(opw, wot);
    gemm_nt<<<dim3(4, 4),  256>>>(ipw, wot, nullptr, Mf, 256, 256, 256, 0);   // Mf = Wq@Wo
    gemm_nt<<<dim3(4, 16), 256>>>(wih, wot, nullptr, W2, 1024, 256, 256, 0);  // W2 = w_ih@Wo
    k_pack<<<256, 256>>>(whh, pk);

    // --- ve / gen1 ---
    k_hid<<<3200, 256>>>(st, tlw, tlb, hid);
    gemm_nt<<<dim3(4, 200), 256>>>(hid, tuw, tub, ve, 12800, 256, 64, 0);     // tenc -> ve
    k_ve<<<12800, 256>>>(seqs, emb, nn, pn, sa, sb, ve, g1);

    // --- K/V projections of gen1 ---
    gemm_nt<<<dim3(4, 200), 256>>>(g1, ipw + 256 * 256, ipb + 256, kp, 12800, 256, 256, 0);
    gemm_nt<<<dim3(4, 200), 256>>>(g1, ipw + 512 * 256, ipb + 512, vp, 12800, 256, 256, 0);

    // --- LSTM gate pre-activations for the ve branch ---
    gemm_nt<<<dim3(16, 200), 256>>>(ve, wih, bsum, xgv, 12800, 1024, 256, 0);

    // --- 50 serial attention steps ---
    for (int s = 0; s < VV; s++)
        k_attn<<<dim3(8, 16), 256, ATTN_SHM_BYTES>>>(s, kp, vp, O, Mf, cf, qp0);

    // --- LSTM gate pre-activations for the gen branch (Wo folded into W2) ---
    gemm_nt<<<dim3(16, 200), 256>>>(O, W2, b2, xgg, 12800, 1024, 256, 0);

    // --- LSTMs: 25 clusters x 2 CTAs, 4 chains per CTA ---
    k_lstm<<<50, 512, LSTM_SHM_BYTES>>>(xgv, xgg, pk, H);

    // --- classifier ---
    gemm_nt<<<dim3(16, 2), 256>>>(H,  c1w, c1b, H1, 100, 1024, 256, 1);
    gemm_nt<<<dim3(16, 2), 256>>>(H1, c2w, c2b, H2, 100, 1024, 1024, 1);
    k_logits<<<1, 128>>>(H2, cow, cob, prob);

    // --- outputs ---
    k_out<<<204, 256>>>(prob, out);
    cudaMemcpyAsync(out + 52224,           nn, (size_t)BB * VV * DD * sizeof(float),
                    cudaMemcpyDeviceToDevice);
    cudaMemcpyAsync(out + 52224 + 3276800, pn, (size_t)BB * VV * DD * sizeof(float),
                    cudaMemcpyDeviceToDevice);
}